// round 2
// baseline (speedup 1.0000x reference)
#include <cuda_runtime.h>

// Problem constants
#define BB 8
#define NN 128
#define CC 64
#define INV_AVG (1.0f/49.0f)
#define NEG_SLOPE 0.01f

// ---------------- scratch (device globals; no allocation) ----------------
__device__ __align__(16) float g_CB[128*64];        // GEMM B: k<64 -> C[op3][d][s], k>=64 -> C[op4][d][s]
__device__ __align__(16) float g_Wmat[192*192];     // stats->U/V/Dg weight matrix
__device__ __align__(16) float g_stats[BB*NN*192];  // per token: [diag(64) | rowsum/49(64) | colsum/49(64)]
__device__ float g_trace[BB*CC];                    // /49
__device__ float g_asum[BB*CC];                     // /49^2
__device__ float g_W2[BB*2*CC];                     // per-batch: [W | Wd]
__device__ __align__(16) float g_U [BB*NN*CC];      // i-indexed adds (+W+bias)
__device__ __align__(16) float g_V [BB*NN*CC];      // j-indexed adds
__device__ __align__(16) float g_Dg[BB*NN*CC];      // diagonal adds (+Wd+diag_bias)

// packed fp32 fma: acc(2xf32) += a(2xf32) * b(2xf32)
__device__ __forceinline__ void ffma2(unsigned long long &acc, unsigned long long a, unsigned long long b) {
    asm("fma.rn.f32x2 %0, %1, %2, %0;" : "+l"(acc) : "l"(a), "l"(b));
}

// ---------------- P0a: combined coef matrix for the main GEMM ----------------
__global__ void cb_kernel(const float* __restrict__ c00, const float* __restrict__ c01,
                          const float* __restrict__ c10, const float* __restrict__ c11) {
    int idx = blockIdx.x * blockDim.x + threadIdx.x;   // 8192 = 128*64
    if (idx >= 128*64) return;
    int s = idx & 63;
    int k = idx >> 6;
    int d = k & 63;
    int bop = (k < 64) ? 3 : 4;   // op3 = identity, op4 = transpose
    g_CB[idx] = c00[d*15 + bop] * c10[d*64 + s] + c01[s*15 + bop] * c11[d*64 + s];
}

// ---------------- P0b: stats->outputs weight matrix [192 x 192] ----------------
// k = (kind<<6)|d with kind: 0=diag, 1=rowsum, 2=colsum
// o = (group<<6)|s with group: 0=U (i-bcast), 1=V (j-bcast), 2=Dg (diagonal)
__global__ void wmat_kernel(const float* __restrict__ c00, const float* __restrict__ c01,
                            const float* __restrict__ c10, const float* __restrict__ c11) {
    int idx = blockIdx.x * blockDim.x + threadIdx.x;   // 36864
    if (idx >= 192*192) return;
    int o = idx % 192;
    int k = idx / 192;
    int g = o >> 6, s = o & 63;
    int kk = k >> 6, d = k & 63;
    // basis op index per (group, stat kind)
    const int opmap[3][3] = { {1, 9, 11},    // U : diag->op1, rowsum->op9, colsum->op11
                              {2, 10, 12},   // V : diag->op2, rowsum->op10, colsum->op12
                              {0, 5, 6} };   // Dg: diag->op0, rowsum->op5, colsum->op6
    int op = opmap[g][kk];
    g_Wmat[idx] = c00[d*15 + op] * c10[d*64 + s] + c01[s*15 + op] * c11[d*64 + s];
}

// ---------------- P1: per-token stats ----------------
__global__ void stats_kernel(const float* __restrict__ in) {
    int bt = blockIdx.x;            // 0..1023
    int b = bt >> 7, t = bt & 127;
    int tid = threadIdx.x;          // 256
    int d  = tid & 63;
    int jl = tid >> 6;              // 0..3

    const float* rowbase = in + (size_t)((b*NN + t) * NN) * CC;   // in[b,t,j,d]
    float rs = 0.f;
    for (int j = jl; j < NN; j += 4) rs += rowbase[j*CC + d];

    const float* colbase = in + ((size_t)b*NN*NN + t) * CC;       // in[b,i,t,d]
    float cs = 0.f;
    for (int i = jl; i < NN; i += 4) cs += colbase[(size_t)i*NN*CC + d];

    __shared__ float red[2][4][64];
    red[0][jl][d] = rs;
    red[1][jl][d] = cs;
    __syncthreads();
    if (jl == 0) {
        float r = red[0][0][d] + red[0][1][d] + red[0][2][d] + red[0][3][d];
        float c = red[1][0][d] + red[1][1][d] + red[1][2][d] + red[1][3][d];
        int o = (b*NN + t)*192;
        g_stats[o + d]       = rowbase[t*CC + d];   // diag
        g_stats[o + 64 + d]  = r * INV_AVG;         // rowsum
        g_stats[o + 128 + d] = c * INV_AVG;         // colsum
    }
}

// ---------------- P1b: trace / allsum ----------------
__global__ void trace_kernel() {
    int b = blockIdx.x;     // 8
    int d = threadIdx.x;    // 64
    float tr = 0.f, as = 0.f;
    for (int t = 0; t < NN; t++) {
        tr += g_stats[(b*NN + t)*192 + d];
        as += g_stats[(b*NN + t)*192 + 64 + d];
    }
    g_trace[b*CC + d] = tr * INV_AVG;
    g_asum [b*CC + d] = as * INV_AVG;
}

// ---------------- P1c: per-batch W / Wd ----------------
__global__ void w2_kernel(const float* __restrict__ c00, const float* __restrict__ c01,
                          const float* __restrict__ c10, const float* __restrict__ c11) {
    int b = blockIdx.x;     // 8
    int s = threadIdx.x;    // 64
    float W = 0.f, Wd = 0.f;
    for (int d = 0; d < 64; d++) {
        float f10 = c10[d*64 + s], f11 = c11[d*64 + s];
        float tr = g_trace[b*CC + d], as = g_asum[b*CC + d];
        float C13 = c00[d*15 + 13]*f10 + c01[s*15 + 13]*f11;
        float C14 = c00[d*15 + 14]*f10 + c01[s*15 + 14]*f11;
        float C7  = c00[d*15 + 7 ]*f10 + c01[s*15 + 7 ]*f11;
        float C8  = c00[d*15 + 8 ]*f10 + c01[s*15 + 8 ]*f11;
        W  += tr*C13 + as*C14;
        Wd += tr*C7  + as*C8;
    }
    g_W2[(b*2 + 0)*CC + s] = W;
    g_W2[(b*2 + 1)*CC + s] = Wd;
}

// ---------------- P2: stats GEMM -> U/V/Dg  (M=1024, K=192, N=192) ----------------
__global__ __launch_bounds__(256) void cgemm_kernel(const float* __restrict__ bias,
                                                    const float* __restrict__ dbias) {
    int tok0 = blockIdx.x * 64;     // 16 blocks
    int n0   = blockIdx.y * 64;     // 3 blocks (one output group per by)
    int tid = threadIdx.x;
    int tx = tid & 15, ty = tid >> 4;

    __shared__ float sS[16][68];
    __shared__ float sW[16][64];

    float acc[4][4];
#pragma unroll
    for (int r = 0; r < 4; r++)
#pragma unroll
        for (int c = 0; c < 4; c++) acc[r][c] = 0.f;

    for (int k0 = 0; k0 < 192; k0 += 16) {
        {   // stats tile, transposed: sS[k][m]
            int m = tid & 63, kq = tid >> 6;
            float4 v = *(const float4*)&g_stats[(tok0 + m)*192 + k0 + kq*4];
            sS[kq*4+0][m] = v.x; sS[kq*4+1][m] = v.y;
            sS[kq*4+2][m] = v.z; sS[kq*4+3][m] = v.w;
        }
        {   // weight tile
            int kk = tid >> 4, n4 = (tid & 15) * 4;
            *(float4*)&sW[kk][n4] = *(const float4*)&g_Wmat[(k0 + kk)*192 + n0 + n4];
        }
        __syncthreads();
#pragma unroll
        for (int kk = 0; kk < 16; kk++) {
            float4 a = *(const float4*)&sS[kk][ty*4];
            float4 b = *(const float4*)&sW[kk][tx*4];
            float av[4] = {a.x, a.y, a.z, a.w};
            float bv[4] = {b.x, b.y, b.z, b.w};
#pragma unroll
            for (int r = 0; r < 4; r++)
#pragma unroll
                for (int c = 0; c < 4; c++) acc[r][c] += av[r] * bv[c];
        }
        __syncthreads();
    }

    int g = n0 >> 6;               // output group for this by
    int b = tok0 >> 7;             // batch (64-token tile never crosses batches)
#pragma unroll
    for (int r = 0; r < 4; r++) {
        int tok = tok0 + ty*4 + r;
#pragma unroll
        for (int c = 0; c < 4; c++) {
            int s = (n0 & 63) + tx*4 + c;   // n0&63 == 0 always; s = tx*4+c
            float v = acc[r][c];
            int oi = tok*CC + s;
            if (g == 0)      g_U[oi]  = v + g_W2[(b*2 + 0)*CC + s] + bias[s];
            else if (g == 1) g_V[oi]  = v;
            else             g_Dg[oi] = v + g_W2[(b*2 + 1)*CC + s] + dbias[s];
        }
    }
}

// ---------------- P3: main fused GEMM + epilogue (packed f32x2) ----------------
// Per CTA: b, two consecutive i rows -> M = 256 positions (m = il*128 + j), N = 64 (s), K = 128.
// A[m,k]: k<64 -> in[b,i,j,k];  k>=64 -> in[b,j,i,k-64].  B = g_CB (duplicated in smem).
// Pairs packed along m; acc[c][p] holds (m=2p, m=2p+1) at s-col c.
#define SA_STRIDE 260

__global__ __launch_bounds__(256, 2) void main_kernel(const float* __restrict__ in,
                                                      const float* __restrict__ mask,
                                                      float* __restrict__ out) {
    int b  = blockIdx.x >> 6;
    int i0 = (blockIdx.x & 63) * 2;
    int tid  = threadIdx.x;
    int sidx = tid & 7;    // -> s = sidx*8 .. +7
    int midx = tid >> 3;   // -> m = midx*8 .. +7

    __shared__ float sA[16][SA_STRIDE];
    __shared__ float sBd[16][128];     // B duplicated: sBd[kk][2s] = sBd[kk][2s+1] = B[kk][s]

    unsigned long long acc[8][4];      // [s-col c][m-pair p]
#pragma unroll
    for (int c = 0; c < 8; c++)
#pragma unroll
        for (int p = 0; p < 4; p++) acc[c][p] = 0ull;

    const float* Abase = in + (size_t)b * NN * NN * CC;

    for (int kt = 0; kt < 8; kt++) {
        int k0 = kt * 16;
        // load B tile (16 x 64) duplicated
        {
            int kk = tid >> 4, sc = (tid & 15) * 4;
            float4 v = *(const float4*)&g_CB[(k0 + kk)*64 + sc];
            float* dst = &sBd[kk][sc*2];
            dst[0] = v.x; dst[1] = v.x; dst[2] = v.y; dst[3] = v.y;
            dst[4] = v.z; dst[5] = v.z; dst[6] = v.w; dst[7] = v.w;
        }
        // load A tile (256 m x 16 k), transposed into sA[kk][m]
#pragma unroll
        for (int p = 0; p < 4; p++) {
            int q  = tid + p*256;
            int m  = q >> 2;
            int kg = q & 3;
            int k  = k0 + kg*4;
            int i  = i0 + (m >> 7);
            int j  = m & 127;
            const float4* src;
            if (k < 64) src = (const float4*)(Abase + ((size_t)(i*NN + j))*CC + k);
            else        src = (const float4*)(Abase + ((size_t)(j*NN + i))*CC + (k - 64));
            float4 v = *src;
            sA[kg*4+0][m] = v.x;
            sA[kg*4+1][m] = v.y;
            sA[kg*4+2][m] = v.z;
            sA[kg*4+3][m] = v.w;
        }
        __syncthreads();

#pragma unroll
        for (int kk = 0; kk < 16; kk++) {
            ulonglong2 a01 = *(const ulonglong2*)&sA[kk][midx*8];
            ulonglong2 a23 = *(const ulonglong2*)&sA[kk][midx*8 + 4];
            unsigned long long ap[4] = {a01.x, a01.y, a23.x, a23.y};
            ulonglong2 b01 = *(const ulonglong2*)&sBd[kk][sidx*16];
            ulonglong2 b23 = *(const ulonglong2*)&sBd[kk][sidx*16 + 4];
            ulonglong2 b45 = *(const ulonglong2*)&sBd[kk][sidx*16 + 8];
            ulonglong2 b67 = *(const ulonglong2*)&sBd[kk][sidx*16 + 12];
            unsigned long long bp[8] = {b01.x, b01.y, b23.x, b23.y,
                                        b45.x, b45.y, b67.x, b67.y};
#pragma unroll
            for (int c = 0; c < 8; c++)
#pragma unroll
                for (int p = 0; p < 4; p++) ffma2(acc[c][p], ap[p], bp[c]);
        }
        __syncthreads();
    }

    // epilogue
    int s0 = sidx * 8;
#pragma unroll
    for (int p = 0; p < 4; p++) {
#pragma unroll
        for (int e = 0; e < 2; e++) {
            int m = midx*8 + p*2 + e;
            int i = i0 + (m >> 7);
            int j = m & 127;
            int uo = (b*NN + i)*CC + s0;
            int vo = (b*NN + j)*CC + s0;
            float mk = mask[(b*NN + i)*NN + j];
            bool on_diag = (i == j);
            size_t oo = ((size_t)(b*NN + i)*NN + j)*CC + s0;
#pragma unroll
            for (int c = 0; c < 8; c++) {
                float2 f2 = *reinterpret_cast<float2*>(&acc[c][p]);
                float v = (e ? f2.y : f2.x) + g_U[uo + c] + g_V[vo + c];
                if (on_diag) v += g_Dg[uo + c];
                v = (v > 0.f) ? v : NEG_SLOPE * v;
                out[oo + c] = v * mk;
            }
        }
    }
}

// ---------------- launch ----------------
extern "C" void kernel_launch(void* const* d_in, const int* in_sizes, int n_in,
                              void* d_out, int out_size) {
    const float* in     = (const float*)d_in[0];
    const float* mask   = (const float*)d_in[1];
    // d_in[2] = nobj (unused: reference hard-codes average_nobj = 49)
    const float* c00    = (const float*)d_in[3];
    const float* c01    = (const float*)d_in[4];
    const float* c10    = (const float*)d_in[5];
    const float* c11    = (const float*)d_in[6];
    const float* bias   = (const float*)d_in[7];
    const float* dbias  = (const float*)d_in[8];
    float* out = (float*)d_out;

    cb_kernel<<<32, 256>>>(c00, c01, c10, c11);
    wmat_kernel<<<144, 256>>>(c00, c01, c10, c11);
    stats_kernel<<<BB*NN, 256>>>(in);
    trace_kernel<<<BB, 64>>>();
    w2_kernel<<<BB, 64>>>(c00, c01, c10, c11);
    cgemm_kernel<<<dim3(16, 3), 256>>>(bias, dbias);
    main_kernel<<<BB*64, 256>>>(in, mask, out);
}

// round 3
// speedup vs baseline: 1.7912x; 1.7912x over previous
#include <cuda_runtime.h>

// Problem constants
#define BB 8
#define NN 128
#define CC 64
#define INV_AVG (1.0f/49.0f)
#define NEG_SLOPE 0.01f

// ---------------- scratch (device globals; no allocation) ----------------
__device__ __align__(16) float g_CB[128*64];        // GEMM B: k<64 -> C[op3][d][s], k>=64 -> C[op4][d][s]
__device__ __align__(16) float g_Wmat[192*192];     // stats->U/V/Dg weight matrix
__device__ __align__(16) float g_stats[BB*NN*192];  // per token: [diag(64) | rowsum/49(64) | colsum/49(64)]
__device__ float g_W2[BB*2*CC];                     // per-batch: [W | Wd]
__device__ __align__(16) float g_U [BB*NN*CC];      // i-indexed adds (+W+bias)
__device__ __align__(16) float g_V [BB*NN*CC];      // j-indexed adds
__device__ __align__(16) float g_Dg[BB*NN*CC];      // diagonal adds (+Wd+diag_bias)

// ---------------- P0: all coefficient tables in one launch ----------------
// idx < 8192          -> g_CB   [128 x 64]
// idx >= 8192 (36864) -> g_Wmat [192 x 192]
__global__ void coef_kernel(const float* __restrict__ c00, const float* __restrict__ c01,
                            const float* __restrict__ c10, const float* __restrict__ c11) {
    int idx = blockIdx.x * blockDim.x + threadIdx.x;   // 45056 total
    if (idx < 8192) {
        int s = idx & 63;
        int k = idx >> 6;
        int d = k & 63;
        int bop = (k < 64) ? 3 : 4;   // op3 = identity, op4 = transpose
        g_CB[idx] = c00[d*15 + bop] * c10[d*64 + s] + c01[s*15 + bop] * c11[d*64 + s];
        return;
    }
    int w = idx - 8192;
    if (w >= 192*192) return;
    int o = w % 192;
    int k = w / 192;
    int g = o >> 6, s = o & 63;
    int kk = k >> 6, d = k & 63;
    const int opmap[3][3] = { {1, 9, 11},    // U : diag, rowsum, colsum
                              {2, 10, 12},   // V
                              {0, 5, 6} };   // Dg
    int op = opmap[g][kk];
    g_Wmat[w] = c00[d*15 + op] * c10[d*64 + s] + c01[s*15 + op] * c11[d*64 + s];
}

// ---------------- P1: per-token stats ----------------
__global__ void stats_kernel(const float* __restrict__ in) {
    int bt = blockIdx.x;            // 0..1023
    int b = bt >> 7, t = bt & 127;
    int tid = threadIdx.x;          // 256
    int d  = tid & 63;
    int jl = tid >> 6;              // 0..3

    const float* rowbase = in + (size_t)((b*NN + t) * NN) * CC;   // in[b,t,j,d]
    float rs = 0.f;
    for (int j = jl; j < NN; j += 4) rs += rowbase[j*CC + d];

    const float* colbase = in + ((size_t)b*NN*NN + t) * CC;       // in[b,i,t,d]
    float cs = 0.f;
    for (int i = jl; i < NN; i += 4) cs += colbase[(size_t)i*NN*CC + d];

    __shared__ float red[2][4][64];
    red[0][jl][d] = rs;
    red[1][jl][d] = cs;
    __syncthreads();
    if (jl == 0) {
        float r = red[0][0][d] + red[0][1][d] + red[0][2][d] + red[0][3][d];
        float c = red[1][0][d] + red[1][1][d] + red[1][2][d] + red[1][3][d];
        int o = (b*NN + t)*192;
        g_stats[o + d]       = rowbase[t*CC + d];   // diag
        g_stats[o + 64 + d]  = r * INV_AVG;         // rowsum
        g_stats[o + 128 + d] = c * INV_AVG;         // colsum
    }
}

// ---------------- P1b: fused trace/allsum reduction + per-batch W/Wd ----------------
// One block per batch, 256 threads. Phase 1: parallel-over-t reduction of
// diag & rowsum into trace/allsum (in smem). Phase 2: threads 0..63 compute W/Wd.
__global__ __launch_bounds__(256) void tw_kernel(const float* __restrict__ c00,
                                                 const float* __restrict__ c01,
                                                 const float* __restrict__ c10,
                                                 const float* __restrict__ c11) {
    int b = blockIdx.x;     // 8
    int tid = threadIdx.x;
    int d = tid & 63, part = tid >> 6;   // 4 partials per d

    float tr = 0.f, as = 0.f;
    const float* sb = g_stats + (size_t)(b*NN)*192;
    for (int t = part; t < NN; t += 4) {
        tr += sb[t*192 + d];
        as += sb[t*192 + 64 + d];
    }
    __shared__ float red[2][4][64];
    __shared__ float strace[64], sasum[64];
    red[0][part][d] = tr;
    red[1][part][d] = as;
    __syncthreads();
    if (part == 0) {
        strace[d] = (red[0][0][d] + red[0][1][d] + red[0][2][d] + red[0][3][d]) * INV_AVG;
        sasum [d] = (red[1][0][d] + red[1][1][d] + red[1][2][d] + red[1][3][d]) * INV_AVG;
    }
    __syncthreads();

    if (tid < 64) {
        int s = tid;
        float c13b = c01[s*15 + 13], c14b = c01[s*15 + 14];
        float c7b  = c01[s*15 + 7],  c8b  = c01[s*15 + 8];
        float W = 0.f, Wd = 0.f;
        for (int dd = 0; dd < 64; dd++) {
            float f10 = c10[dd*64 + s], f11 = c11[dd*64 + s];
            float t0 = strace[dd], a0 = sasum[dd];
            W  += t0*(c00[dd*15 + 13]*f10 + c13b*f11) + a0*(c00[dd*15 + 14]*f10 + c14b*f11);
            Wd += t0*(c00[dd*15 + 7 ]*f10 + c7b *f11) + a0*(c00[dd*15 + 8 ]*f10 + c8b *f11);
        }
        g_W2[(b*2 + 0)*CC + s] = W;
        g_W2[(b*2 + 1)*CC + s] = Wd;
    }
}

// ---------------- P2: stats GEMM -> U/V/Dg  (M=1024, K=192, N=192) ----------------
__global__ __launch_bounds__(256) void cgemm_kernel(const float* __restrict__ bias,
                                                    const float* __restrict__ dbias) {
    int tok0 = blockIdx.x * 64;     // 16 blocks
    int n0   = blockIdx.y * 64;     // 3 blocks (one output group per by)
    int tid = threadIdx.x;
    int tx = tid & 15, ty = tid >> 4;

    __shared__ float sS[16][68];
    __shared__ float sW[16][64];

    float acc[4][4];
#pragma unroll
    for (int r = 0; r < 4; r++)
#pragma unroll
        for (int c = 0; c < 4; c++) acc[r][c] = 0.f;

    for (int k0 = 0; k0 < 192; k0 += 16) {
        {   // stats tile, transposed: sS[k][m]
            int m = tid & 63, kq = tid >> 6;
            float4 v = *(const float4*)&g_stats[(tok0 + m)*192 + k0 + kq*4];
            sS[kq*4+0][m] = v.x; sS[kq*4+1][m] = v.y;
            sS[kq*4+2][m] = v.z; sS[kq*4+3][m] = v.w;
        }
        {   // weight tile
            int kk = tid >> 4, n4 = (tid & 15) * 4;
            *(float4*)&sW[kk][n4] = *(const float4*)&g_Wmat[(k0 + kk)*192 + n0 + n4];
        }
        __syncthreads();
#pragma unroll
        for (int kk = 0; kk < 16; kk++) {
            float4 a = *(const float4*)&sS[kk][ty*4];
            float4 b = *(const float4*)&sW[kk][tx*4];
            float av[4] = {a.x, a.y, a.z, a.w};
            float bv[4] = {b.x, b.y, b.z, b.w};
#pragma unroll
            for (int r = 0; r < 4; r++)
#pragma unroll
                for (int c = 0; c < 4; c++) acc[r][c] += av[r] * bv[c];
        }
        __syncthreads();
    }

    int g = n0 >> 6;               // output group for this by
    int b = tok0 >> 7;             // batch (64-token tile never crosses batches)
#pragma unroll
    for (int r = 0; r < 4; r++) {
        int tok = tok0 + ty*4 + r;
#pragma unroll
        for (int c = 0; c < 4; c++) {
            int s = tx*4 + c;
            float v = acc[r][c];
            int oi = tok*CC + s;
            if (g == 0)      g_U[oi]  = v + g_W2[(b*2 + 0)*CC + s] + bias[s];
            else if (g == 1) g_V[oi]  = v;
            else             g_Dg[oi] = v + g_W2[(b*2 + 1)*CC + s] + dbias[s];
        }
    }
}

// ---------------- P3: main fused GEMM + epilogue ----------------
// Per CTA: b, two consecutive i rows -> M = 256 positions (m = il*128 + j), N = 64 (s), K = 128.
// A[m,k]: k<64 -> in[b,i,j,k];  k>=64 -> in[b,j,i,k-64].  B = g_CB.
// Epilogue: + U[b,i,s] + V[b,j,s] + (i==j)*Dg[b,i,s]; leaky-relu; * mask.
#define SA_STRIDE 260

__global__ __launch_bounds__(256, 2) void main_kernel(const float* __restrict__ in,
                                                      const float* __restrict__ mask,
                                                      float* __restrict__ out) {
    int b  = blockIdx.x >> 6;
    int i0 = (blockIdx.x & 63) * 2;
    int tid  = threadIdx.x;
    int sidx = tid & 7;    // -> s = sidx*8 .. +7
    int midx = tid >> 3;   // -> m = midx*8 .. +7

    __shared__ float sA[16][SA_STRIDE];
    __shared__ float sB[16][64];

    float acc[8][8];
#pragma unroll
    for (int r = 0; r < 8; r++)
#pragma unroll
        for (int c = 0; c < 8; c++) acc[r][c] = 0.f;

    const float* Abase = in + (size_t)b * NN * NN * CC;

    for (int kt = 0; kt < 8; kt++) {
        int k0 = kt * 16;
        // load B tile (16 x 64)
        {
            int kk = tid >> 4, sc = (tid & 15) * 4;
            *(float4*)&sB[kk][sc] = *(const float4*)&g_CB[(k0 + kk)*64 + sc];
        }
        // load A tile (256 m x 16 k), transposed into sA[kk][m]
#pragma unroll
        for (int p = 0; p < 4; p++) {
            int q  = tid + p*256;
            int m  = q >> 2;
            int kg = q & 3;
            int k  = k0 + kg*4;
            int i  = i0 + (m >> 7);
            int j  = m & 127;
            const float4* src;
            if (k < 64) src = (const float4*)(Abase + ((size_t)(i*NN + j))*CC + k);
            else        src = (const float4*)(Abase + ((size_t)(j*NN + i))*CC + (k - 64));
            float4 v = *src;
            sA[kg*4+0][m] = v.x;
            sA[kg*4+1][m] = v.y;
            sA[kg*4+2][m] = v.z;
            sA[kg*4+3][m] = v.w;
        }
        __syncthreads();

#pragma unroll
        for (int kk = 0; kk < 16; kk++) {
            float4 a0 = *(const float4*)&sA[kk][midx*8];
            float4 a1 = *(const float4*)&sA[kk][midx*8 + 4];
            float4 b0 = *(const float4*)&sB[kk][sidx*8];
            float4 b1 = *(const float4*)&sB[kk][sidx*8 + 4];
            float av[8] = {a0.x, a0.y, a0.z, a0.w, a1.x, a1.y, a1.z, a1.w};
            float bv[8] = {b0.x, b0.y, b0.z, b0.w, b1.x, b1.y, b1.z, b1.w};
#pragma unroll
            for (int r = 0; r < 8; r++)
#pragma unroll
                for (int c = 0; c < 8; c++) acc[r][c] += av[r] * bv[c];
        }
        __syncthreads();
    }

    // epilogue
    int s0 = sidx * 8;
#pragma unroll
    for (int r = 0; r < 8; r++) {
        int m = midx*8 + r;
        int i = i0 + (m >> 7);
        int j = m & 127;
        int uo = (b*NN + i)*CC + s0;
        int vo = (b*NN + j)*CC + s0;
        float mk = mask[(b*NN + i)*NN + j];
        bool on_diag = (i == j);
        size_t oo = ((size_t)(b*NN + i)*NN + j)*CC + s0;
#pragma unroll
        for (int c = 0; c < 8; c++) {
            float v = acc[r][c] + g_U[uo + c] + g_V[vo + c];
            if (on_diag) v += g_Dg[uo + c];
            v = (v > 0.f) ? v : NEG_SLOPE * v;
            out[oo + c] = v * mk;
        }
    }
}

// ---------------- launch ----------------
extern "C" void kernel_launch(void* const* d_in, const int* in_sizes, int n_in,
                              void* d_out, int out_size) {
    const float* in     = (const float*)d_in[0];
    const float* mask   = (const float*)d_in[1];
    // d_in[2] = nobj (unused: reference hard-codes average_nobj = 49)
    const float* c00    = (const float*)d_in[3];
    const float* c01    = (const float*)d_in[4];
    const float* c10    = (const float*)d_in[5];
    const float* c11    = (const float*)d_in[6];
    const float* bias   = (const float*)d_in[7];
    const float* dbias  = (const float*)d_in[8];
    float* out = (float*)d_out;

    coef_kernel<<<176, 256>>>(c00, c01, c10, c11);
    stats_kernel<<<BB*NN, 256>>>(in);
    tw_kernel<<<BB, 256>>>(c00, c01, c10, c11);
    cgemm_kernel<<<dim3(16, 3), 256>>>(bias, dbias);
    main_kernel<<<BB*64, 256>>>(in, mask, out);
}

// round 4
// speedup vs baseline: 1.8483x; 1.0319x over previous
#include <cuda_runtime.h>

// Problem constants
#define BB 8
#define NN 128
#define CC 64
#define INV_AVG (1.0f/49.0f)
#define NEG_SLOPE 0.01f

// ---------------- scratch (device globals; no allocation) ----------------
__device__ __align__(16) float g_CB[128*64];        // GEMM B: k<64 -> C[op3][d][s], k>=64 -> C[op4][d][s]
__device__ __align__(16) float g_stats[BB*NN*192];  // per token: [diag(64) | rowsum/49(64) | colsum/49(64)]
__device__ float g_W2[BB*2*CC];                     // per-batch: [W | Wd]
__device__ __align__(16) float g_U [BB*NN*CC];      // i-indexed adds (+W+bias)
__device__ __align__(16) float g_V [BB*NN*CC];      // j-indexed adds
__device__ __align__(16) float g_Dg[BB*NN*CC];      // diagonal adds (+Wd+diag_bias)

// ---------------- P1: per-token stats (+ side job: build g_CB) ----------------
__global__ void stats_kernel(const float* __restrict__ in,
                             const float* __restrict__ c00, const float* __restrict__ c01,
                             const float* __restrict__ c10, const float* __restrict__ c11) {
    int bt = blockIdx.x;            // 0..1023
    int b = bt >> 7, t = bt & 127;
    int tid = threadIdx.x;          // 256
    int d  = tid & 63;
    int jl = tid >> 6;              // 0..3

    // side job: first 32 blocks build the main-GEMM B matrix (one elem/thread)
    if (bt < 32) {
        int idx = bt * 256 + tid;   // 8192 = 128*64
        int s = idx & 63;
        int k = idx >> 6;
        int dd = k & 63;
        int bop = (k < 64) ? 3 : 4; // op3 = identity, op4 = transpose
        g_CB[idx] = c00[dd*15 + bop] * c10[dd*64 + s] + c01[s*15 + bop] * c11[dd*64 + s];
    }

    const float* rowbase = in + (size_t)((b*NN + t) * NN) * CC;   // in[b,t,j,d]
    float rs = 0.f;
    for (int j = jl; j < NN; j += 4) rs += rowbase[j*CC + d];

    const float* colbase = in + ((size_t)b*NN*NN + t) * CC;       // in[b,i,t,d]
    float cs = 0.f;
    for (int i = jl; i < NN; i += 4) cs += colbase[(size_t)i*NN*CC + d];

    __shared__ float red[2][4][64];
    red[0][jl][d] = rs;
    red[1][jl][d] = cs;
    __syncthreads();
    if (jl == 0) {
        float r = red[0][0][d] + red[0][1][d] + red[0][2][d] + red[0][3][d];
        float c = red[1][0][d] + red[1][1][d] + red[1][2][d] + red[1][3][d];
        int o = (b*NN + t)*192;
        g_stats[o + d]       = rowbase[t*CC + d];   // diag
        g_stats[o + 64 + d]  = r * INV_AVG;         // rowsum
        g_stats[o + 128 + d] = c * INV_AVG;         // colsum
    }
}

// ---------------- P1b: fused trace/allsum reduction + per-batch W/Wd ----------------
__global__ __launch_bounds__(256) void tw_kernel(const float* __restrict__ c00,
                                                 const float* __restrict__ c01,
                                                 const float* __restrict__ c10,
                                                 const float* __restrict__ c11) {
    int b = blockIdx.x;     // 8
    int tid = threadIdx.x;
    int d = tid & 63, part = tid >> 6;   // 4 partials per d

    float tr = 0.f, as = 0.f;
    const float* sb = g_stats + (size_t)(b*NN)*192;
#pragma unroll 4
    for (int t = part; t < NN; t += 4) {
        tr += sb[t*192 + d];
        as += sb[t*192 + 64 + d];
    }
    __shared__ float red[2][4][64];
    __shared__ float strace[64], sasum[64];
    red[0][part][d] = tr;
    red[1][part][d] = as;
    __syncthreads();
    if (part == 0) {
        strace[d] = (red[0][0][d] + red[0][1][d] + red[0][2][d] + red[0][3][d]) * INV_AVG;
        sasum [d] = (red[1][0][d] + red[1][1][d] + red[1][2][d] + red[1][3][d]) * INV_AVG;
    }
    __syncthreads();

    if (tid < 64) {
        int s = tid;
        float c13b = c01[s*15 + 13], c14b = c01[s*15 + 14];
        float c7b  = c01[s*15 + 7],  c8b  = c01[s*15 + 8];
        float W = 0.f, Wd = 0.f;
#pragma unroll 4
        for (int dd = 0; dd < 64; dd++) {
            float f10 = c10[dd*64 + s], f11 = c11[dd*64 + s];
            float t0 = strace[dd], a0 = sasum[dd];
            W  += t0*(c00[dd*15 + 13]*f10 + c13b*f11) + a0*(c00[dd*15 + 14]*f10 + c14b*f11);
            Wd += t0*(c00[dd*15 + 7 ]*f10 + c7b *f11) + a0*(c00[dd*15 + 8 ]*f10 + c8b *f11);
        }
        g_W2[(b*2 + 0)*CC + s] = W;
        g_W2[(b*2 + 1)*CC + s] = Wd;
    }
}

// ---------------- P2: stats GEMM -> U/V/Dg  (M=1024, K=192, N=192) ----------------
// grid (64, 3): bx = 16-token tile, by = output group g (0=U, 1=V, 2=Dg).
// Weight slice computed in-CTA from coef factors (no precomputed Wmat).
// K processed in two 96-row phases to fit static smem.
__global__ __launch_bounds__(256) void cgemm_kernel(const float* __restrict__ c00,
                                                    const float* __restrict__ c01,
                                                    const float* __restrict__ c10,
                                                    const float* __restrict__ c11,
                                                    const float* __restrict__ bias,
                                                    const float* __restrict__ dbias) {
    int tok0 = blockIdx.x * 16;
    int g    = blockIdx.y;
    int tid  = threadIdx.x;
    int ty   = tid >> 4;        // token 0..15
    int sq   = tid & 15;        // s-quad

    const int opmap[3][3] = { {1, 9, 11},    // U : diag, rowsum, colsum
                              {2, 10, 12},   // V
                              {0, 5, 6} };   // Dg
    int op0 = opmap[g][0], op1 = opmap[g][1], op2 = opmap[g][2];

    __shared__ float sS[16][196];   // stats [tok][k]
    __shared__ float sW[96][64];    // weight phase slice [k][s]

    // load stats tile: 16 tok x 192 k = 3072 floats, float4 x 3/thread
#pragma unroll
    for (int q = 0; q < 3; q++) {
        int e = tid + q*256;            // 0..767 quads
        int tk = e / 48;                // token
        int kq = e % 48;                // k-quad
        float4 v = *(const float4*)&g_stats[(tok0 + tk)*192 + kq*4];
        *(float4*)&sS[tk][kq*4] = v;
    }

    float acc[4] = {0.f, 0.f, 0.f, 0.f};

#pragma unroll
    for (int ph = 0; ph < 2; ph++) {
        int kbase = ph * 96;
        __syncthreads();   // protect sW reuse across phases
        // build weight slice rows kbase..kbase+95: 6144 elems, 24/thread
#pragma unroll
        for (int q = 0; q < 24; q++) {
            int e = tid + q*256;
            int s = e & 63;
            int kl = e >> 6;            // 0..95
            int k = kbase + kl;
            int kind = k >> 6, d = k & 63;
            int op = (kind == 0) ? op0 : (kind == 1) ? op1 : op2;
            sW[kl][s] = c00[d*15 + op] * c10[d*64 + s] + c01[s*15 + op] * c11[d*64 + s];
        }
        __syncthreads();

#pragma unroll 8
        for (int kl = 0; kl < 96; kl++) {
            float a = sS[ty][kbase + kl];
            float4 w = *(const float4*)&sW[kl][sq*4];
            acc[0] += a * w.x;
            acc[1] += a * w.y;
            acc[2] += a * w.z;
            acc[3] += a * w.w;
        }
    }

    int tok = tok0 + ty;
    int b = tok >> 7;
    int s0 = sq * 4;
    int oi = tok*CC + s0;
#pragma unroll
    for (int c = 0; c < 4; c++) {
        int s = s0 + c;
        float v = acc[c];
        if (g == 0)      g_U[oi + c]  = v + g_W2[(b*2 + 0)*CC + s] + bias[s];
        else if (g == 1) g_V[oi + c]  = v;
        else             g_Dg[oi + c] = v + g_W2[(b*2 + 1)*CC + s] + dbias[s];
    }
}

// ---------------- P3: main fused GEMM + epilogue ----------------
// Per CTA: b, two consecutive i rows -> M = 256 positions (m = il*128 + j), N = 64 (s), K = 128.
// A[m,k]: k<64 -> in[b,i,j,k];  k>=64 -> in[b,j,i,k-64].  B = g_CB.
// Epilogue: + U[b,i,s] + V[b,j,s] + (i==j)*Dg[b,i,s]; leaky-relu; * mask.
#define SA_STRIDE 260

__global__ __launch_bounds__(256, 2) void main_kernel(const float* __restrict__ in,
                                                      const float* __restrict__ mask,
                                                      float* __restrict__ out) {
    int b  = blockIdx.x >> 6;
    int i0 = (blockIdx.x & 63) * 2;
    int tid  = threadIdx.x;
    int sidx = tid & 7;    // -> s = sidx*8 .. +7
    int midx = tid >> 3;   // -> m = midx*8 .. +7

    __shared__ float sA[16][SA_STRIDE];
    __shared__ float sB[16][64];

    float acc[8][8];
#pragma unroll
    for (int r = 0; r < 8; r++)
#pragma unroll
        for (int c = 0; c < 8; c++) acc[r][c] = 0.f;

    const float* Abase = in + (size_t)b * NN * NN * CC;

    for (int kt = 0; kt < 8; kt++) {
        int k0 = kt * 16;
        // load B tile (16 x 64)
        {
            int kk = tid >> 4, sc = (tid & 15) * 4;
            *(float4*)&sB[kk][sc] = *(const float4*)&g_CB[(k0 + kk)*64 + sc];
        }
        // load A tile (256 m x 16 k), transposed into sA[kk][m]
#pragma unroll
        for (int p = 0; p < 4; p++) {
            int q  = tid + p*256;
            int m  = q >> 2;
            int kg = q & 3;
            int k  = k0 + kg*4;
            int i  = i0 + (m >> 7);
            int j  = m & 127;
            const float4* src;
            if (k < 64) src = (const float4*)(Abase + ((size_t)(i*NN + j))*CC + k);
            else        src = (const float4*)(Abase + ((size_t)(j*NN + i))*CC + (k - 64));
            float4 v = *src;
            sA[kg*4+0][m] = v.x;
            sA[kg*4+1][m] = v.y;
            sA[kg*4+2][m] = v.z;
            sA[kg*4+3][m] = v.w;
        }
        __syncthreads();

#pragma unroll
        for (int kk = 0; kk < 16; kk++) {
            float4 a0 = *(const float4*)&sA[kk][midx*8];
            float4 a1 = *(const float4*)&sA[kk][midx*8 + 4];
            float4 b0 = *(const float4*)&sB[kk][sidx*8];
            float4 b1 = *(const float4*)&sB[kk][sidx*8 + 4];
            float av[8] = {a0.x, a0.y, a0.z, a0.w, a1.x, a1.y, a1.z, a1.w};
            float bv[8] = {b0.x, b0.y, b0.z, b0.w, b1.x, b1.y, b1.z, b1.w};
#pragma unroll
            for (int r = 0; r < 8; r++)
#pragma unroll
                for (int c = 0; c < 8; c++) acc[r][c] += av[r] * bv[c];
        }
        __syncthreads();
    }

    // epilogue
    int s0 = sidx * 8;
#pragma unroll
    for (int r = 0; r < 8; r++) {
        int m = midx*8 + r;
        int i = i0 + (m >> 7);
        int j = m & 127;
        int uo = (b*NN + i)*CC + s0;
        int vo = (b*NN + j)*CC + s0;
        float mk = mask[(b*NN + i)*NN + j];
        bool on_diag = (i == j);
        size_t oo = ((size_t)(b*NN + i)*NN + j)*CC + s0;
#pragma unroll
        for (int c = 0; c < 8; c++) {
            float v = acc[r][c] + g_U[uo + c] + g_V[vo + c];
            if (on_diag) v += g_Dg[uo + c];
            v = (v > 0.f) ? v : NEG_SLOPE * v;
            out[oo + c] = v * mk;
        }
    }
}

// ---------------- launch ----------------
extern "C" void kernel_launch(void* const* d_in, const int* in_sizes, int n_in,
                              void* d_out, int out_size) {
    const float* in     = (const float*)d_in[0];
    const float* mask   = (const float*)d_in[1];
    // d_in[2] = nobj (unused: reference hard-codes average_nobj = 49)
    const float* c00    = (const float*)d_in[3];
    const float* c01    = (const float*)d_in[4];
    const float* c10    = (const float*)d_in[5];
    const float* c11    = (const float*)d_in[6];
    const float* bias   = (const float*)d_in[7];
    const float* dbias  = (const float*)d_in[8];
    float* out = (float*)d_out;

    stats_kernel<<<BB*NN, 256>>>(in, c00, c01, c10, c11);
    tw_kernel<<<BB, 256>>>(c00, c01, c10, c11);
    cgemm_kernel<<<dim3(64, 3), 256>>>(c00, c01, c10, c11, bias, dbias);
    main_kernel<<<BB*64, 256>>>(in, mask, out);
}

// round 5
// speedup vs baseline: 2.3095x; 1.2495x over previous
#include <cuda_runtime.h>

// Problem constants
#define BB 8
#define NN 128
#define CC 64
#define INV_AVG (1.0f/49.0f)
#define NEG_SLOPE 0.01f

// ---------------- scratch (device globals; no allocation) ----------------
__device__ __align__(16) float g_CB[128*64];        // GEMM B: k<64 -> C[op3][d][s], k>=64 -> C[op4][d][s]
__device__ __align__(16) float g_stats[BB*NN*192];  // per token: [diag(64) | rowsum/49(64) | colsum/49(64)]
__device__ float g_W2[BB*2*CC];                     // per-batch: [W | Wd]
__device__ __align__(16) float g_U [BB*NN*CC];      // i-indexed adds (+W+bias)
__device__ __align__(16) float g_V [BB*NN*CC];      // j-indexed adds
__device__ __align__(16) float g_Dg[BB*NN*CC];      // diagonal adds (+Wd+diag_bias)

__device__ __forceinline__ void cpa16(unsigned dst, const void* src) {
    asm volatile("cp.async.cg.shared.global [%0], [%1], 16;" :: "r"(dst), "l"(src));
}
__device__ __forceinline__ void cpa_commit() {
    asm volatile("cp.async.commit_group;");
}
template <int N>
__device__ __forceinline__ void cpa_wait() {
    asm volatile("cp.async.wait_group %0;" :: "n"(N));
}

// ---------------- P1: per-token stats (+ side job: build g_CB) ----------------
__global__ void stats_kernel(const float* __restrict__ in,
                             const float* __restrict__ c00, const float* __restrict__ c01,
                             const float* __restrict__ c10, const float* __restrict__ c11) {
    int bt = blockIdx.x;            // 0..1023
    int b = bt >> 7, t = bt & 127;
    int tid = threadIdx.x;          // 256
    int d  = tid & 63;
    int jl = tid >> 6;              // 0..3

    // side job: first 32 blocks build the main-GEMM B matrix (one elem/thread)
    if (bt < 32) {
        int idx = bt * 256 + tid;   // 8192 = 128*64
        int s = idx & 63;
        int k = idx >> 6;
        int dd = k & 63;
        int bop = (k < 64) ? 3 : 4; // op3 = identity, op4 = transpose
        g_CB[idx] = c00[dd*15 + bop] * c10[dd*64 + s] + c01[s*15 + bop] * c11[dd*64 + s];
    }

    const float* rowbase = in + (size_t)((b*NN + t) * NN) * CC;   // in[b,t,j,d]
    float rs = 0.f;
    for (int j = jl; j < NN; j += 4) rs += rowbase[j*CC + d];

    const float* colbase = in + ((size_t)b*NN*NN + t) * CC;       // in[b,i,t,d]
    float cs = 0.f;
    for (int i = jl; i < NN; i += 4) cs += colbase[(size_t)i*NN*CC + d];

    __shared__ float red[2][4][64];
    red[0][jl][d] = rs;
    red[1][jl][d] = cs;
    __syncthreads();
    if (jl == 0) {
        float r = red[0][0][d] + red[0][1][d] + red[0][2][d] + red[0][3][d];
        float c = red[1][0][d] + red[1][1][d] + red[1][2][d] + red[1][3][d];
        int o = (b*NN + t)*192;
        g_stats[o + d]       = rowbase[t*CC + d];   // diag
        g_stats[o + 64 + d]  = r * INV_AVG;         // rowsum
        g_stats[o + 128 + d] = c * INV_AVG;         // colsum
    }
}

// ---------------- P1b: fused trace/allsum reduction + per-batch W/Wd ----------------
__global__ __launch_bounds__(256) void tw_kernel(const float* __restrict__ c00,
                                                 const float* __restrict__ c01,
                                                 const float* __restrict__ c10,
                                                 const float* __restrict__ c11) {
    int b = blockIdx.x;     // 8
    int tid = threadIdx.x;
    int d = tid & 63, part = tid >> 6;   // 4 partials per d

    float tr = 0.f, as = 0.f;
    const float* sb = g_stats + (size_t)(b*NN)*192;
#pragma unroll 4
    for (int t = part; t < NN; t += 4) {
        tr += sb[t*192 + d];
        as += sb[t*192 + 64 + d];
    }
    __shared__ float red[2][4][64];
    __shared__ float strace[64], sasum[64];
    red[0][part][d] = tr;
    red[1][part][d] = as;
    __syncthreads();
    if (part == 0) {
        strace[d] = (red[0][0][d] + red[0][1][d] + red[0][2][d] + red[0][3][d]) * INV_AVG;
        sasum [d] = (red[1][0][d] + red[1][1][d] + red[1][2][d] + red[1][3][d]) * INV_AVG;
    }
    __syncthreads();

    if (tid < 64) {
        int s = tid;
        float c13b = c01[s*15 + 13], c14b = c01[s*15 + 14];
        float c7b  = c01[s*15 + 7],  c8b  = c01[s*15 + 8];
        float W = 0.f, Wd = 0.f;
#pragma unroll 4
        for (int dd = 0; dd < 64; dd++) {
            float f10 = c10[dd*64 + s], f11 = c11[dd*64 + s];
            float t0 = strace[dd], a0 = sasum[dd];
            W  += t0*(c00[dd*15 + 13]*f10 + c13b*f11) + a0*(c00[dd*15 + 14]*f10 + c14b*f11);
            Wd += t0*(c00[dd*15 + 7 ]*f10 + c7b *f11) + a0*(c00[dd*15 + 8 ]*f10 + c8b *f11);
        }
        g_W2[(b*2 + 0)*CC + s] = W;
        g_W2[(b*2 + 1)*CC + s] = Wd;
    }
}

// ---------------- P2: stats GEMM -> U/V/Dg  (M=1024, K=192, N=192) ----------------
__global__ __launch_bounds__(256) void cgemm_kernel(const float* __restrict__ c00,
                                                    const float* __restrict__ c01,
                                                    const float* __restrict__ c10,
                                                    const float* __restrict__ c11,
                                                    const float* __restrict__ bias,
                                                    const float* __restrict__ dbias) {
    int tok0 = blockIdx.x * 16;
    int g    = blockIdx.y;
    int tid  = threadIdx.x;
    int ty   = tid >> 4;        // token 0..15
    int sq   = tid & 15;        // s-quad

    const int opmap[3][3] = { {1, 9, 11},    // U : diag, rowsum, colsum
                              {2, 10, 12},   // V
                              {0, 5, 6} };   // Dg
    int op0 = opmap[g][0], op1 = opmap[g][1], op2 = opmap[g][2];

    __shared__ float sS[16][196];   // stats [tok][k]
    __shared__ float sW[96][64];    // weight phase slice [k][s]

#pragma unroll
    for (int q = 0; q < 3; q++) {
        int e = tid + q*256;            // 0..767 quads
        int tk = e / 48;
        int kq = e % 48;
        float4 v = *(const float4*)&g_stats[(tok0 + tk)*192 + kq*4];
        *(float4*)&sS[tk][kq*4] = v;
    }

    float acc[4] = {0.f, 0.f, 0.f, 0.f};

#pragma unroll
    for (int ph = 0; ph < 2; ph++) {
        int kbase = ph * 96;
        __syncthreads();
#pragma unroll
        for (int q = 0; q < 24; q++) {
            int e = tid + q*256;
            int s = e & 63;
            int kl = e >> 6;            // 0..95
            int k = kbase + kl;
            int kind = k >> 6, d = k & 63;
            int op = (kind == 0) ? op0 : (kind == 1) ? op1 : op2;
            sW[kl][s] = c00[d*15 + op] * c10[d*64 + s] + c01[s*15 + op] * c11[d*64 + s];
        }
        __syncthreads();

#pragma unroll 8
        for (int kl = 0; kl < 96; kl++) {
            float a = sS[ty][kbase + kl];
            float4 w = *(const float4*)&sW[kl][sq*4];
            acc[0] += a * w.x;
            acc[1] += a * w.y;
            acc[2] += a * w.z;
            acc[3] += a * w.w;
        }
    }

    int tok = tok0 + ty;
    int b = tok >> 7;
    int s0 = sq * 4;
    int oi = tok*CC + s0;
#pragma unroll
    for (int c = 0; c < 4; c++) {
        int s = s0 + c;
        float v = acc[c];
        if (g == 0)      g_U[oi + c]  = v + g_W2[(b*2 + 0)*CC + s] + bias[s];
        else if (g == 1) g_V[oi + c]  = v;
        else             g_Dg[oi + c] = v + g_W2[(b*2 + 1)*CC + s] + dbias[s];
    }
}

// ---------------- P3: main fused GEMM + epilogue ----------------
// Per CTA: b, two consecutive i rows -> M = 256 (m = h*128 + j), N = 64 (s), K = 128.
// A kept natural [m][k] in smem (cp.async, double-buffered).
// Register tile: 4+4 split in both m and s (conflict-free B float4, broadcast A scalar).
__global__ __launch_bounds__(256, 2) void main_kernel(const float* __restrict__ in,
                                                      const float* __restrict__ mask,
                                                      float* __restrict__ out) {
    int b  = blockIdx.x >> 6;
    int i0 = (blockIdx.x & 63) * 2;
    int tid  = threadIdx.x;
    int sidx = tid & 7;    // s quads: sidx*4, 32+sidx*4
    int midx = tid >> 3;   // m quads: midx*4, 128+midx*4

    __shared__ float sA[2][256][16];
    __shared__ float sB[2][16][64];

    unsigned sA0 = (unsigned)__cvta_generic_to_shared(&sA[0][0][0]);
    unsigned sB0 = (unsigned)__cvta_generic_to_shared(&sB[0][0][0]);

    const float* Abase = in + (size_t)b * NN * NN * CC;

    // per-thread prefetch geometry (constant across kt)
    int pm[4], pkg[4];
#pragma unroll
    for (int p = 0; p < 4; p++) {
        int q = tid + p*256;
        pm[p]  = q >> 2;       // m
        pkg[p] = q & 3;        // k-quad within 16
    }

    // prefetch tile kt into buffer bufi
    auto prefetch = [&](int kt, int bufi) {
        int k0 = kt * 16;
        bool tr = (k0 >= 64);
        int kb = tr ? (k0 - 64) : k0;
#pragma unroll
        for (int p = 0; p < 4; p++) {
            int m = pm[p];
            int i = i0 + (m >> 7);
            int j = m & 127;
            const float* src = tr ? (Abase + ((size_t)(j*NN + i))*CC + kb + pkg[p]*4)
                                  : (Abase + ((size_t)(i*NN + j))*CC + kb + pkg[p]*4);
            unsigned dst = sA0 + (unsigned)((bufi*256*16 + m*16 + pkg[p]*4) * 4);
            cpa16(dst, src);
        }
        {   // B tile: 16x64 floats = 256 chunks, one per thread
            int kk = tid >> 4, c4 = (tid & 15) * 4;
            unsigned dst = sB0 + (unsigned)((bufi*16*64 + kk*64 + c4) * 4);
            cpa16(dst, &g_CB[(k0 + kk)*64 + c4]);
        }
        cpa_commit();
    };

    float acc[2][4][8];    // [m half][r][s (2 halves x 4)]
#pragma unroll
    for (int h = 0; h < 2; h++)
#pragma unroll
        for (int r = 0; r < 4; r++)
#pragma unroll
            for (int c = 0; c < 8; c++) acc[h][r][c] = 0.f;

    prefetch(0, 0);

#pragma unroll 1
    for (int kt = 0; kt < 8; kt++) {
        int cur = kt & 1;
        if (kt < 7) {
            prefetch(kt + 1, cur ^ 1);
            cpa_wait<1>();
        } else {
            cpa_wait<0>();
        }
        __syncthreads();

#pragma unroll
        for (int kk = 0; kk < 16; kk++) {
            float a[2][4];
#pragma unroll
            for (int h = 0; h < 2; h++)
#pragma unroll
                for (int r = 0; r < 4; r++)
                    a[h][r] = sA[cur][h*128 + midx*4 + r][kk];
            float4 b0 = *(const float4*)&sB[cur][kk][sidx*4];
            float4 b1 = *(const float4*)&sB[cur][kk][32 + sidx*4];
            float bv[8] = {b0.x, b0.y, b0.z, b0.w, b1.x, b1.y, b1.z, b1.w};
#pragma unroll
            for (int h = 0; h < 2; h++)
#pragma unroll
                for (int r = 0; r < 4; r++)
#pragma unroll
                    for (int c = 0; c < 8; c++)
                        acc[h][r][c] += a[h][r] * bv[c];
        }
        __syncthreads();
    }

    // epilogue: + U[b,i,s] + V[b,j,s] + diag*Dg; leaky-relu; * mask
#pragma unroll
    for (int h = 0; h < 2; h++) {
        int i = i0 + h;
        int uo = (b*NN + i)*CC;
        float4 u0 = *(const float4*)&g_U[uo + sidx*4];
        float4 u1 = *(const float4*)&g_U[uo + 32 + sidx*4];
        float uv[8] = {u0.x, u0.y, u0.z, u0.w, u1.x, u1.y, u1.z, u1.w};
#pragma unroll
        for (int r = 0; r < 4; r++) {
            int j = midx*4 + r;
            int vo = (b*NN + j)*CC;
            float4 v0 = *(const float4*)&g_V[vo + sidx*4];
            float4 v1 = *(const float4*)&g_V[vo + 32 + sidx*4];
            float vv[8] = {v0.x, v0.y, v0.z, v0.w, v1.x, v1.y, v1.z, v1.w};
            float mk = mask[(b*NN + i)*NN + j];
            bool on_diag = (i == j);
            float dgv[8];
            if (on_diag) {
                float4 d0 = *(const float4*)&g_Dg[uo + sidx*4];
                float4 d1 = *(const float4*)&g_Dg[uo + 32 + sidx*4];
                dgv[0]=d0.x; dgv[1]=d0.y; dgv[2]=d0.z; dgv[3]=d0.w;
                dgv[4]=d1.x; dgv[5]=d1.y; dgv[6]=d1.z; dgv[7]=d1.w;
            }
            float o[8];
#pragma unroll
            for (int c = 0; c < 8; c++) {
                float v = acc[h][r][c] + uv[c] + vv[c];
                if (on_diag) v += dgv[c];
                v = (v > 0.f) ? v : NEG_SLOPE * v;
                o[c] = v * mk;
            }
            size_t oo = ((size_t)(b*NN + i)*NN + j)*CC;
            *(float4*)&out[oo + sidx*4]      = make_float4(o[0], o[1], o[2], o[3]);
            *(float4*)&out[oo + 32 + sidx*4] = make_float4(o[4], o[5], o[6], o[7]);
        }
    }
}

// ---------------- launch ----------------
extern "C" void kernel_launch(void* const* d_in, const int* in_sizes, int n_in,
                              void* d_out, int out_size) {
    const float* in     = (const float*)d_in[0];
    const float* mask   = (const float*)d_in[1];
    // d_in[2] = nobj (unused: reference hard-codes average_nobj = 49)
    const float* c00    = (const float*)d_in[3];
    const float* c01    = (const float*)d_in[4];
    const float* c10    = (const float*)d_in[5];
    const float* c11    = (const float*)d_in[6];
    const float* bias   = (const float*)d_in[7];
    const float* dbias  = (const float*)d_in[8];
    float* out = (float*)d_out;

    stats_kernel<<<BB*NN, 256>>>(in, c00, c01, c10, c11);
    tw_kernel<<<BB, 256>>>(c00, c01, c10, c11);
    cgemm_kernel<<<dim3(64, 3), 256>>>(c00, c01, c10, c11, bias, dbias);
    main_kernel<<<BB*64, 256>>>(in, mask, out);
}

// round 7
// speedup vs baseline: 2.6904x; 1.1650x over previous
#include <cuda_runtime.h>
#include <cuda_bf16.h>
#include <cstdint>
#include <cstring>

// Problem constants
#define BB 8
#define NN 128
#define CC 64
#define INV_AVG (1.0f/49.0f)
#define NEG_SLOPE 0.01f

// ---------------- scratch (device globals; no allocation) ----------------
// bf16 hi/lo B tables for the tensor GEMM, stored [s][k] (col-major B for row.col mma)
__device__ __align__(16) __nv_bfloat16 g_Bhi[64*128];
__device__ __align__(16) __nv_bfloat16 g_Blo[64*128];
__device__ __align__(16) float g_stats[BB*NN*192];  // per token: [diag | rowsum/49 | colsum/49]
__device__ float g_W2[BB*2*CC];                     // per-batch: [W | Wd]
__device__ __align__(16) float g_U [BB*NN*CC];      // i-indexed adds (+W+bias)
__device__ __align__(16) float g_V [BB*NN*CC];      // j-indexed adds
__device__ __align__(16) float g_Dg[BB*NN*CC];      // diagonal adds (+Wd+diag_bias)

// ---------------- PTX helpers ----------------
__device__ __forceinline__ void cpa16(unsigned dst, const void* src) {
    asm volatile("cp.async.cg.shared.global [%0], [%1], 16;" :: "r"(dst), "l"(src));
}
__device__ __forceinline__ void cpa_commit() { asm volatile("cp.async.commit_group;"); }
template <int N> __device__ __forceinline__ void cpa_wait() {
    asm volatile("cp.async.wait_group %0;" :: "n"(N));
}

__device__ __forceinline__ void ldm_x4(uint32_t* r, uint32_t addr) {
    asm volatile("ldmatrix.sync.aligned.m8n8.x4.shared.b16 {%0,%1,%2,%3}, [%4];"
                 : "=r"(r[0]), "=r"(r[1]), "=r"(r[2]), "=r"(r[3]) : "r"(addr));
}

__device__ __forceinline__ void mma_bf16(float* c, const uint32_t* a, const uint32_t* b) {
    asm volatile("mma.sync.aligned.m16n8k16.row.col.f32.bf16.bf16.f32 "
                 "{%0,%1,%2,%3}, {%4,%5,%6,%7}, {%8,%9}, {%0,%1,%2,%3};"
                 : "+f"(c[0]), "+f"(c[1]), "+f"(c[2]), "+f"(c[3])
                 : "r"(a[0]), "r"(a[1]), "r"(a[2]), "r"(a[3]), "r"(b[0]), "r"(b[1]));
}

// ---------------- P1: per-token stats (+ side job: build bf16 hi/lo B tables) ----------------
__global__ void stats_kernel(const float* __restrict__ in,
                             const float* __restrict__ c00, const float* __restrict__ c01,
                             const float* __restrict__ c10, const float* __restrict__ c11) {
    int bt = blockIdx.x;            // 0..1023
    int b = bt >> 7, t = bt & 127;
    int tid = threadIdx.x;          // 256
    int d  = tid & 63;
    int jl = tid >> 6;              // 0..3

    // side job: first 32 blocks build B[k][s] -> stored transposed as [s][k] bf16 hi/lo
    if (bt < 32) {
        int idx = bt * 256 + tid;   // 8192 = 128*64
        int s = idx & 63;
        int k = idx >> 6;
        int dd = k & 63;
        int bop = (k < 64) ? 3 : 4; // op3 = identity, op4 = transpose
        float v = c00[dd*15 + bop] * c10[dd*64 + s] + c01[s*15 + bop] * c11[dd*64 + s];
        __nv_bfloat16 hi = __float2bfloat16(v);
        __nv_bfloat16 lo = __float2bfloat16(v - __bfloat162float(hi));
        g_Bhi[s*128 + k] = hi;
        g_Blo[s*128 + k] = lo;
    }

    const float* rowbase = in + (size_t)((b*NN + t) * NN) * CC;   // in[b,t,j,d]
    float rs = 0.f;
    for (int j = jl; j < NN; j += 4) rs += rowbase[j*CC + d];

    const float* colbase = in + ((size_t)b*NN*NN + t) * CC;       // in[b,i,t,d]
    float cs = 0.f;
    for (int i = jl; i < NN; i += 4) cs += colbase[(size_t)i*NN*CC + d];

    __shared__ float red[2][4][64];
    red[0][jl][d] = rs;
    red[1][jl][d] = cs;
    __syncthreads();
    if (jl == 0) {
        float r = red[0][0][d] + red[0][1][d] + red[0][2][d] + red[0][3][d];
        float c = red[1][0][d] + red[1][1][d] + red[1][2][d] + red[1][3][d];
        int o = (b*NN + t)*192;
        g_stats[o + d]       = rowbase[t*CC + d];   // diag
        g_stats[o + 64 + d]  = r * INV_AVG;         // rowsum
        g_stats[o + 128 + d] = c * INV_AVG;         // colsum
    }
}

// ---------------- P1b: fused trace/allsum reduction + per-batch W/Wd ----------------
__global__ __launch_bounds__(256) void tw_kernel(const float* __restrict__ c00,
                                                 const float* __restrict__ c01,
                                                 const float* __restrict__ c10,
                                                 const float* __restrict__ c11) {
    int b = blockIdx.x;     // 8
    int tid = threadIdx.x;
    int d = tid & 63, part = tid >> 6;   // 4 partials per d

    float tr = 0.f, as = 0.f;
    const float* sb = g_stats + (size_t)(b*NN)*192;
#pragma unroll 4
    for (int t = part; t < NN; t += 4) {
        tr += sb[t*192 + d];
        as += sb[t*192 + 64 + d];
    }
    __shared__ float red[2][4][64];
    __shared__ float strace[64], sasum[64];
    red[0][part][d] = tr;
    red[1][part][d] = as;
    __syncthreads();
    if (part == 0) {
        strace[d] = (red[0][0][d] + red[0][1][d] + red[0][2][d] + red[0][3][d]) * INV_AVG;
        sasum [d] = (red[1][0][d] + red[1][1][d] + red[1][2][d] + red[1][3][d]) * INV_AVG;
    }
    __syncthreads();

    if (tid < 64) {
        int s = tid;
        float c13b = c01[s*15 + 13], c14b = c01[s*15 + 14];
        float c7b  = c01[s*15 + 7],  c8b  = c01[s*15 + 8];
        float W = 0.f, Wd = 0.f;
#pragma unroll 4
        for (int dd = 0; dd < 64; dd++) {
            float f10 = c10[dd*64 + s], f11 = c11[dd*64 + s];
            float t0 = strace[dd], a0 = sasum[dd];
            W  += t0*(c00[dd*15 + 13]*f10 + c13b*f11) + a0*(c00[dd*15 + 14]*f10 + c14b*f11);
            Wd += t0*(c00[dd*15 + 7 ]*f10 + c7b *f11) + a0*(c00[dd*15 + 8 ]*f10 + c8b *f11);
        }
        g_W2[(b*2 + 0)*CC + s] = W;
        g_W2[(b*2 + 1)*CC + s] = Wd;
    }
}

// ---------------- P2: stats GEMM -> U/V/Dg  (M=1024, K=192, N=192) ----------------
__global__ __launch_bounds__(256) void cgemm_kernel(const float* __restrict__ c00,
                                                    const float* __restrict__ c01,
                                                    const float* __restrict__ c10,
                                                    const float* __restrict__ c11,
                                                    const float* __restrict__ bias,
                                                    const float* __restrict__ dbias) {
    int tok0 = blockIdx.x * 16;
    int g    = blockIdx.y;
    int tid  = threadIdx.x;
    int ty   = tid >> 4;        // token 0..15
    int sq   = tid & 15;        // s-quad

    const int opmap[3][3] = { {1, 9, 11},    // U : diag, rowsum, colsum
                              {2, 10, 12},   // V
                              {0, 5, 6} };   // Dg
    int op0 = opmap[g][0], op1 = opmap[g][1], op2 = opmap[g][2];

    __shared__ float sS[16][196];   // stats [tok][k]
    __shared__ float sW[96][64];    // weight phase slice [k][s]

#pragma unroll
    for (int q = 0; q < 3; q++) {
        int e = tid + q*256;            // 0..767 quads
        int tk = e / 48;
        int kq = e % 48;
        float4 v = *(const float4*)&g_stats[(tok0 + tk)*192 + kq*4];
        *(float4*)&sS[tk][kq*4] = v;
    }

    float acc[4] = {0.f, 0.f, 0.f, 0.f};

#pragma unroll
    for (int ph = 0; ph < 2; ph++) {
        int kbase = ph * 96;
        __syncthreads();
#pragma unroll
        for (int q = 0; q < 24; q++) {
            int e = tid + q*256;
            int s = e & 63;
            int kl = e >> 6;            // 0..95
            int k = kbase + kl;
            int kind = k >> 6, d = k & 63;
            int op = (kind == 0) ? op0 : (kind == 1) ? op1 : op2;
            sW[kl][s] = c00[d*15 + op] * c10[d*64 + s] + c01[s*15 + op] * c11[d*64 + s];
        }
        __syncthreads();

#pragma unroll 8
        for (int kl = 0; kl < 96; kl++) {
            float a = sS[ty][kbase + kl];
            float4 w = *(const float4*)&sW[kl][sq*4];
            acc[0] += a * w.x;
            acc[1] += a * w.y;
            acc[2] += a * w.z;
            acc[3] += a * w.w;
        }
    }

    int tok = tok0 + ty;
    int b = tok >> 7;
    int s0 = sq * 4;
    int oi = tok*CC + s0;
#pragma unroll
    for (int c = 0; c < 4; c++) {
        int s = s0 + c;
        float v = acc[c];
        if (g == 0)      g_U[oi + c]  = v + g_W2[(b*2 + 0)*CC + s] + bias[s];
        else if (g == 1) g_V[oi + c]  = v;
        else             g_Dg[oi + c] = v + g_W2[(b*2 + 1)*CC + s] + dbias[s];
    }
}

// ---------------- P3: main GEMM on mma.sync (bf16 hi/lo split, 3 products) ----------------
// Grid = 1024 CTAs (b, i). Per CTA: D[j,s] = sum_k A[j,k] * B[k,s], M=128 N=64 K=128.
// A[j,k]: k<64 -> in[b,i,j,k]; k>=64 -> in[b,j,i,k-64], converted to bf16 hi/lo in padded smem.
// B bf16 hi/lo [s][k] from global (cp.async into padded smem).
// 8 warps: 4(m) x 2(n), each 32m x 32n via 2x4 m16n8k16 tiles, 3 products per tile.
#define A_STRIDE 72    // bf16 per row (64 k + 8 pad) -> 144B row; ldmatrix conflict-free
#define B_STRIDE 136   // bf16 per row (128 k + 8 pad) -> 272B row
// dynamic smem: A_hi [128][72], A_lo [128][72], B_hi [64][136], B_lo [64][136]
#define OFF_AHI 0
#define OFF_ALO (128*A_STRIDE*2)
#define OFF_BHI (2*128*A_STRIDE*2)
#define OFF_BLO (OFF_BHI + 64*B_STRIDE*2)
#define DSM_BYTES (OFF_BLO + 64*B_STRIDE*2)

__global__ __launch_bounds__(256, 2) void main_mma_kernel(const float* __restrict__ in,
                                                          const float* __restrict__ mask,
                                                          float* __restrict__ out) {
    extern __shared__ __align__(128) char dsm[];
    __shared__ float sU[64], sDg[64];

    int tid = threadIdx.x;
    int lane = tid & 31;
    int w = tid >> 5;
    int wm = w >> 1;          // 0..3  -> m base = wm*32
    int wn = w & 1;           // 0..1  -> n base = wn*32
    int b = blockIdx.x >> 7;
    int i = blockIdx.x & 127;

    uint32_t sbase = (uint32_t)__cvta_generic_to_shared(dsm);

    if (tid < 64) {
        sU[tid]  = g_U [(b*NN + i)*CC + tid];
        sDg[tid] = g_Dg[(b*NN + i)*CC + tid];
    }

    // ---- B tiles: cp.async global bf16 [s][128] -> padded smem [s][136] ----
    {
#pragma unroll
        for (int p = 0; p < 4; p++) {
            int c = tid + p*256;        // 1024 chunks of 16B per table
            int row = c >> 4, kc = c & 15;
            cpa16(sbase + OFF_BHI + (uint32_t)(row*B_STRIDE*2 + kc*16),
                  (const char*)g_Bhi + row*256 + kc*16);
            cpa16(sbase + OFF_BLO + (uint32_t)(row*B_STRIDE*2 + kc*16),
                  (const char*)g_Blo + row*256 + kc*16);
        }
        cpa_commit();
    }

    // ldmatrix lane geometry
    int lr = lane & 7;
    int a_row = ((lane >> 3) & 1)*8 + lr;       // matrices: m0k0, m8k0, m0k8, m8k8
    int a_col = ((lane >> 4) & 1)*8;
    int b_row = ((lane >> 4) & 1)*8 + lr;       // matrices: n0k0, n0k8, n8k0, n8k8
    int b_col = ((lane >> 3) & 1)*8;

    const float* Ab = in + (size_t)b * NN * NN * CC;
    int cj = tid >> 1;                 // conversion row (0..127)
    int ch = (tid & 1) * 32;           // conversion col base

    float acc[2][4][4];
#pragma unroll
    for (int mt = 0; mt < 2; mt++)
#pragma unroll
        for (int nt = 0; nt < 4; nt++)
#pragma unroll
            for (int e = 0; e < 4; e++) acc[mt][nt][e] = 0.f;

    bool bwaited = false;

#pragma unroll
    for (int khalf = 0; khalf < 2; khalf++) {
        // ---- convert A k-half: fp32 -> bf16 hi/lo, padded STS ----
        const float* srcrow = (khalf == 0) ? (Ab + ((size_t)i*NN + cj)*CC)
                                           : (Ab + ((size_t)cj*NN + i)*CC);
#pragma unroll
        for (int c = 0; c < 8; c++) {
            int col = ch + c*4;
            float4 v = *(const float4*)(srcrow + col);
            __nv_bfloat162 h0, h1, l0, l1;
            h0.x = __float2bfloat16(v.x); h0.y = __float2bfloat16(v.y);
            h1.x = __float2bfloat16(v.z); h1.y = __float2bfloat16(v.w);
            l0.x = __float2bfloat16(v.x - __bfloat162float(h0.x));
            l0.y = __float2bfloat16(v.y - __bfloat162float(h0.y));
            l1.x = __float2bfloat16(v.z - __bfloat162float(h1.x));
            l1.y = __float2bfloat16(v.w - __bfloat162float(h1.y));
            uint32_t ha, hb, la, lb;
            memcpy(&ha, &h0, 4); memcpy(&hb, &h1, 4);
            memcpy(&la, &l0, 4); memcpy(&lb, &l1, 4);
            uint32_t off = (uint32_t)(cj*A_STRIDE*2 + col*2);
            asm volatile("st.shared.v2.b32 [%0], {%1, %2};"
                         :: "r"(sbase + OFF_AHI + off), "r"(ha), "r"(hb));
            asm volatile("st.shared.v2.b32 [%0], {%1, %2};"
                         :: "r"(sbase + OFF_ALO + off), "r"(la), "r"(lb));
        }
        if (!bwaited) { cpa_wait<0>(); bwaited = true; }
        __syncthreads();

        // ---- mma over 4 k16 chunks of this half ----
#pragma unroll
        for (int kc = 0; kc < 4; kc++) {
            uint32_t ah[2][4], al[2][4];
#pragma unroll
            for (int mt = 0; mt < 2; mt++) {
                uint32_t aoff = (uint32_t)((wm*32 + mt*16 + a_row)*A_STRIDE*2
                                           + (kc*16 + a_col)*2);
                ldm_x4(ah[mt], sbase + OFF_AHI + aoff);
                ldm_x4(al[mt], sbase + OFF_ALO + aoff);
            }
            uint32_t bh[4][2], bl[4][2];
#pragma unroll
            for (int np = 0; np < 2; np++) {
                uint32_t boff = (uint32_t)((wn*32 + np*16 + b_row)*B_STRIDE*2
                                           + (khalf*64 + kc*16 + b_col)*2);
                uint32_t r[4];
                ldm_x4(r, sbase + OFF_BHI + boff);
                bh[np*2][0] = r[0]; bh[np*2][1] = r[1];
                bh[np*2+1][0] = r[2]; bh[np*2+1][1] = r[3];
                ldm_x4(r, sbase + OFF_BLO + boff);
                bl[np*2][0] = r[0]; bl[np*2][1] = r[1];
                bl[np*2+1][0] = r[2]; bl[np*2+1][1] = r[3];
            }
#pragma unroll
            for (int mt = 0; mt < 2; mt++)
#pragma unroll
                for (int nt = 0; nt < 4; nt++) {
                    mma_bf16(acc[mt][nt], ah[mt], bh[nt]);
                    mma_bf16(acc[mt][nt], ah[mt], bl[nt]);
                    mma_bf16(acc[mt][nt], al[mt], bh[nt]);
                }
        }
        __syncthreads();
    }

    // ---- epilogue: + U[i,s] + V[j,s] + diag*Dg; leaky-relu; * mask ----
    int g4 = lane >> 2, q = lane & 3;
#pragma unroll
    for (int mt = 0; mt < 2; mt++) {
#pragma unroll
        for (int half = 0; half < 2; half++) {
            int j = wm*32 + mt*16 + g4 + half*8;
            float mk = mask[(b*NN + i)*NN + j];
            const float* vr = g_V + (b*NN + j)*CC;
            float* orow = out + ((size_t)(b*NN + i)*NN + j)*CC;
            bool od = (j == i);
#pragma unroll
            for (int nt = 0; nt < 4; nt++) {
                int s0 = wn*32 + nt*8 + q*2;
                float2 vv = *(const float2*)(vr + s0);
                float o0 = acc[mt][nt][half*2+0] + sU[s0]   + vv.x;
                float o1 = acc[mt][nt][half*2+1] + sU[s0+1] + vv.y;
                if (od) { o0 += sDg[s0]; o1 += sDg[s0+1]; }
                o0 = (o0 > 0.f) ? o0 : NEG_SLOPE * o0;
                o1 = (o1 > 0.f) ? o1 : NEG_SLOPE * o1;
                *(float2*)(orow + s0) = make_float2(o0*mk, o1*mk);
            }
        }
    }
}

// ---------------- launch ----------------
extern "C" void kernel_launch(void* const* d_in, const int* in_sizes, int n_in,
                              void* d_out, int out_size) {
    const float* in     = (const float*)d_in[0];
    const float* mask   = (const float*)d_in[1];
    // d_in[2] = nobj (unused: reference hard-codes average_nobj = 49)
    const float* c00    = (const float*)d_in[3];
    const float* c01    = (const float*)d_in[4];
    const float* c10    = (const float*)d_in[5];
    const float* c11    = (const float*)d_in[6];
    const float* bias   = (const float*)d_in[7];
    const float* dbias  = (const float*)d_in[8];
    float* out = (float*)d_out;

    static bool attr_set = false;
    if (!attr_set) {
        cudaFuncSetAttribute(main_mma_kernel,
                             cudaFuncAttributeMaxDynamicSharedMemorySize, DSM_BYTES);
        attr_set = true;
    }

    stats_kernel<<<BB*NN, 256>>>(in, c00, c01, c10, c11);
    tw_kernel<<<BB, 256>>>(c00, c01, c10, c11);
    cgemm_kernel<<<dim3(64, 3), 256>>>(c00, c01, c10, c11, bias, dbias);
    main_mma_kernel<<<BB*NN, 256, DSM_BYTES>>>(in, mask, out);
}

// round 8
// speedup vs baseline: 2.8680x; 1.0660x over previous
#include <cuda_runtime.h>
#include <cuda_bf16.h>
#include <cstdint>
#include <cstring>

// Problem constants
#define BB 8
#define NN 128
#define CC 64
#define INV_AVG (1.0f/49.0f)
#define NEG_SLOPE 0.01f

// ---------------- scratch (device globals; no allocation) ----------------
// B in m16n8k16 fragment order: [kc8 (8)][tile (8)][lane (32)][reg (2)] u32 (2 bf16 each)
__device__ __align__(16) uint32_t g_BfH[4096];
__device__ __align__(16) uint32_t g_BfL[4096];
__device__ __align__(16) float g_stats[BB*NN*192];  // per token: [diag | rowsum/49 | colsum/49]
__device__ float g_W2[BB*2*CC];                     // per-batch: [W | Wd]
__device__ __align__(16) float g_U [BB*NN*CC];      // i-indexed adds (+W+bias)
__device__ __align__(16) float g_V [BB*NN*CC];      // j-indexed adds
__device__ __align__(16) float g_Dg[BB*NN*CC];      // diagonal adds (+Wd+diag_bias)

// ---------------- PTX helpers ----------------
__device__ __forceinline__ void ldm_x4(uint32_t* r, uint32_t addr) {
    asm volatile("ldmatrix.sync.aligned.m8n8.x4.shared.b16 {%0,%1,%2,%3}, [%4];"
                 : "=r"(r[0]), "=r"(r[1]), "=r"(r[2]), "=r"(r[3]) : "r"(addr));
}

__device__ __forceinline__ void mma_bf16(float* c, const uint32_t* a, uint32_t b0, uint32_t b1) {
    asm volatile("mma.sync.aligned.m16n8k16.row.col.f32.bf16.bf16.f32 "
                 "{%0,%1,%2,%3}, {%4,%5,%6,%7}, {%8,%9}, {%0,%1,%2,%3};"
                 : "+f"(c[0]), "+f"(c[1]), "+f"(c[2]), "+f"(c[3])
                 : "r"(a[0]), "r"(a[1]), "r"(a[2]), "r"(a[3]), "r"(b0), "r"(b1));
}

__device__ __forceinline__ uint32_t pk2(__nv_bfloat16 x, __nv_bfloat16 y) {
    __nv_bfloat162 h; h.x = x; h.y = y;
    uint32_t r; memcpy(&r, &h, 4); return r;
}

// ---------------- P1: per-token stats (+ side job: B fragment tables) ----------------
__global__ void stats_kernel(const float* __restrict__ in,
                             const float* __restrict__ c00, const float* __restrict__ c01,
                             const float* __restrict__ c10, const float* __restrict__ c11) {
    int bt = blockIdx.x;            // 0..1023
    int b = bt >> 7, t = bt & 127;
    int tid = threadIdx.x;          // 256
    int d  = tid & 63;
    int jl = tid >> 6;              // 0..3

    // side job: first 32 blocks compute B[k][s] and scatter into fragment order
    if (bt < 32) {
        int idx = bt * 256 + tid;   // 8192 = 128*64
        int s = idx & 63;
        int k = idx >> 6;
        int dd = k & 63;
        int bop = (k < 64) ? 3 : 4; // op3 = identity, op4 = transpose
        float v = c00[dd*15 + bop] * c10[dd*64 + s] + c01[s*15 + bop] * c11[dd*64 + s];
        __nv_bfloat16 hi = __float2bfloat16(v);
        __nv_bfloat16 lo = __float2bfloat16(v - __bfloat162float(hi));
        // m16n8k16 B fragment layout: lane = (n&7)*4 + ((k&7)>>1), reg = (k&15)>>3, elem = k&1
        int kc8 = k >> 4, kr = k & 15;
        int reg = kr >> 3, tg = (kr & 7) >> 1, e = kr & 1;
        int tile = s >> 3, g = s & 7;
        int lane = g*4 + tg;
        int slot = ((kc8*8 + tile)*32 + lane)*2 + reg;
        ((__nv_bfloat16*)g_BfH)[slot*2 + e] = hi;
        ((__nv_bfloat16*)g_BfL)[slot*2 + e] = lo;
    }

    const float* rowbase = in + (size_t)((b*NN + t) * NN) * CC;   // in[b,t,j,d]
    float rs = 0.f;
    for (int j = jl; j < NN; j += 4) rs += rowbase[j*CC + d];

    const float* colbase = in + ((size_t)b*NN*NN + t) * CC;       // in[b,i,t,d]
    float cs = 0.f;
    for (int i = jl; i < NN; i += 4) cs += colbase[(size_t)i*NN*CC + d];

    __shared__ float red[2][4][64];
    red[0][jl][d] = rs;
    red[1][jl][d] = cs;
    __syncthreads();
    if (jl == 0) {
        float r = red[0][0][d] + red[0][1][d] + red[0][2][d] + red[0][3][d];
        float c = red[1][0][d] + red[1][1][d] + red[1][2][d] + red[1][3][d];
        int o = (b*NN + t)*192;
        g_stats[o + d]       = rowbase[t*CC + d];   // diag
        g_stats[o + 64 + d]  = r * INV_AVG;         // rowsum
        g_stats[o + 128 + d] = c * INV_AVG;         // colsum
    }
}

// ---------------- P1b: fused trace/allsum reduction + per-batch W/Wd ----------------
__global__ __launch_bounds__(256) void tw_kernel(const float* __restrict__ c00,
                                                 const float* __restrict__ c01,
                                                 const float* __restrict__ c10,
                                                 const float* __restrict__ c11) {
    int b = blockIdx.x;     // 8
    int tid = threadIdx.x;
    int d = tid & 63, part = tid >> 6;   // 4 partials per d

    float tr = 0.f, as = 0.f;
    const float* sb = g_stats + (size_t)(b*NN)*192;
#pragma unroll 4
    for (int t = part; t < NN; t += 4) {
        tr += sb[t*192 + d];
        as += sb[t*192 + 64 + d];
    }
    __shared__ float red[2][4][64];
    __shared__ float strace[64], sasum[64];
    red[0][part][d] = tr;
    red[1][part][d] = as;
    __syncthreads();
    if (part == 0) {
        strace[d] = (red[0][0][d] + red[0][1][d] + red[0][2][d] + red[0][3][d]) * INV_AVG;
        sasum [d] = (red[1][0][d] + red[1][1][d] + red[1][2][d] + red[1][3][d]) * INV_AVG;
    }
    __syncthreads();

    if (tid < 64) {
        int s = tid;
        float c13b = c01[s*15 + 13], c14b = c01[s*15 + 14];
        float c7b  = c01[s*15 + 7],  c8b  = c01[s*15 + 8];
        float W = 0.f, Wd = 0.f;
#pragma unroll 4
        for (int dd = 0; dd < 64; dd++) {
            float f10 = c10[dd*64 + s], f11 = c11[dd*64 + s];
            float t0 = strace[dd], a0 = sasum[dd];
            W  += t0*(c00[dd*15 + 13]*f10 + c13b*f11) + a0*(c00[dd*15 + 14]*f10 + c14b*f11);
            Wd += t0*(c00[dd*15 + 7 ]*f10 + c7b *f11) + a0*(c00[dd*15 + 8 ]*f10 + c8b *f11);
        }
        g_W2[(b*2 + 0)*CC + s] = W;
        g_W2[(b*2 + 1)*CC + s] = Wd;
    }
}

// ---------------- P2: stats GEMM -> U/V/Dg  (M=1024, K=192, N=192) ----------------
__global__ __launch_bounds__(256) void cgemm_kernel(const float* __restrict__ c00,
                                                    const float* __restrict__ c01,
                                                    const float* __restrict__ c10,
                                                    const float* __restrict__ c11,
                                                    const float* __restrict__ bias,
                                                    const float* __restrict__ dbias) {
    int tok0 = blockIdx.x * 16;
    int g    = blockIdx.y;
    int tid  = threadIdx.x;
    int ty   = tid >> 4;        // token 0..15
    int sq   = tid & 15;        // s-quad

    const int opmap[3][3] = { {1, 9, 11},    // U : diag, rowsum, colsum
                              {2, 10, 12},   // V
                              {0, 5, 6} };   // Dg
    int op0 = opmap[g][0], op1 = opmap[g][1], op2 = opmap[g][2];

    __shared__ float sS[16][196];   // stats [tok][k]
    __shared__ float sW[96][64];    // weight phase slice [k][s]

#pragma unroll
    for (int q = 0; q < 3; q++) {
        int e = tid + q*256;            // 0..767 quads
        int tk = e / 48;
        int kq = e % 48;
        float4 v = *(const float4*)&g_stats[(tok0 + tk)*192 + kq*4];
        *(float4*)&sS[tk][kq*4] = v;
    }

    float acc[4] = {0.f, 0.f, 0.f, 0.f};

#pragma unroll
    for (int ph = 0; ph < 2; ph++) {
        int kbase = ph * 96;
        __syncthreads();
#pragma unroll
        for (int q = 0; q < 24; q++) {
            int e = tid + q*256;
            int s = e & 63;
            int kl = e >> 6;            // 0..95
            int k = kbase + kl;
            int kind = k >> 6, d = k & 63;
            int op = (kind == 0) ? op0 : (kind == 1) ? op1 : op2;
            sW[kl][s] = c00[d*15 + op] * c10[d*64 + s] + c01[s*15 + op] * c11[d*64 + s];
        }
        __syncthreads();

#pragma unroll 8
        for (int kl = 0; kl < 96; kl++) {
            float a = sS[ty][kbase + kl];
            float4 w = *(const float4*)&sW[kl][sq*4];
            acc[0] += a * w.x;
            acc[1] += a * w.y;
            acc[2] += a * w.z;
            acc[3] += a * w.w;
        }
    }

    int tok = tok0 + ty;
    int b = tok >> 7;
    int s0 = sq * 4;
    int oi = tok*CC + s0;
#pragma unroll
    for (int c = 0; c < 4; c++) {
        int s = s0 + c;
        float v = acc[c];
        if (g == 0)      g_U[oi + c]  = v + g_W2[(b*2 + 0)*CC + s] + bias[s];
        else if (g == 1) g_V[oi + c]  = v;
        else             g_Dg[oi + c] = v + g_W2[(b*2 + 1)*CC + s] + dbias[s];
    }
}

// ---------------- P3: main GEMM on mma.sync (bf16 hi/lo, B frags via LDG) ----------------
// Grid = 1024 CTAs (b, i). Per CTA: D[j,s] = sum_k A[j,k] * B[k,s], M=128 N=64 K=128.
// A converted to bf16 hi/lo in XOR-swizzled smem (128 rows x 64 bf16, 128B rows).
// B fragments loaded straight from global (coalesced LDG.64, L2-broadcast hot).
// Epilogue restaged through smem for fully-coalesced V loads + output stores.
#define OFF_AHI 0
#define OFF_ALO 16384
#define ACC_STRIDE 68
#define DSM_BYTES (128*ACC_STRIDE*4)   // 34816 > 32768 (A tables alias this region)

__global__ __launch_bounds__(256, 2) void main_mma_kernel(const float* __restrict__ in,
                                                          const float* __restrict__ mask,
                                                          float* __restrict__ out) {
    extern __shared__ __align__(128) char dsm[];
    __shared__ float sU[64], sDg[64];

    int tid = threadIdx.x;
    int lane = tid & 31;
    int w = tid >> 5;
    int wm = w >> 1;          // 0..3  -> m base = wm*32
    int wn = w & 1;           // 0..1  -> n base = wn*32
    int b = blockIdx.x >> 7;
    int i = blockIdx.x & 127;

    uint32_t sbase = (uint32_t)__cvta_generic_to_shared(dsm);
    float* sAcc = (float*)dsm;

    if (tid < 64) {
        sU[tid]  = g_U [(b*NN + i)*CC + tid];
        sDg[tid] = g_Dg[(b*NN + i)*CC + tid];
    }

    // ldmatrix lane geometry (A)
    int a_row = ((lane >> 3) & 1)*8 + (lane & 7);
    int a_csel = (lane >> 4) & 1;               // chunk select within k16

    const float* Ab = in + (size_t)b * NN * NN * CC;
    int cj = tid >> 1;                 // conversion row (0..127)
    int ch = (tid & 1) * 32;           // conversion fp32 col base

    float acc[2][4][4];
#pragma unroll
    for (int mt = 0; mt < 2; mt++)
#pragma unroll
        for (int nt = 0; nt < 4; nt++)
#pragma unroll
            for (int e = 0; e < 4; e++) acc[mt][nt][e] = 0.f;

#pragma unroll
    for (int khalf = 0; khalf < 2; khalf++) {
        // ---- convert A k-half: fp32 -> bf16 hi/lo, swizzled STS.128 ----
        const float* srcrow = (khalf == 0) ? (Ab + ((size_t)i*NN + cj)*CC)
                                           : (Ab + ((size_t)cj*NN + i)*CC);
#pragma unroll
        for (int c = 0; c < 4; c++) {
            int col = ch + c*8;
            float4 v0 = *(const float4*)(srcrow + col);
            float4 v1 = *(const float4*)(srcrow + col + 4);
            __nv_bfloat16 h0 = __float2bfloat16(v0.x), h1 = __float2bfloat16(v0.y);
            __nv_bfloat16 h2 = __float2bfloat16(v0.z), h3 = __float2bfloat16(v0.w);
            __nv_bfloat16 h4 = __float2bfloat16(v1.x), h5 = __float2bfloat16(v1.y);
            __nv_bfloat16 h6 = __float2bfloat16(v1.z), h7 = __float2bfloat16(v1.w);
            uint32_t H0 = pk2(h0, h1), H1 = pk2(h2, h3), H2 = pk2(h4, h5), H3 = pk2(h6, h7);
            uint32_t L0 = pk2(__float2bfloat16(v0.x - __bfloat162float(h0)),
                              __float2bfloat16(v0.y - __bfloat162float(h1)));
            uint32_t L1 = pk2(__float2bfloat16(v0.z - __bfloat162float(h2)),
                              __float2bfloat16(v0.w - __bfloat162float(h3)));
            uint32_t L2 = pk2(__float2bfloat16(v1.x - __bfloat162float(h4)),
                              __float2bfloat16(v1.y - __bfloat162float(h5)));
            uint32_t L3 = pk2(__float2bfloat16(v1.z - __bfloat162float(h6)),
                              __float2bfloat16(v1.w - __bfloat162float(h7)));
            int chunk = (ch >> 3) + c;                       // 0..7
            uint32_t off = (uint32_t)(cj*128 + ((chunk ^ (cj & 7)) << 4));
            asm volatile("st.shared.v4.b32 [%0], {%1,%2,%3,%4};"
                         :: "r"(sbase + OFF_AHI + off), "r"(H0), "r"(H1), "r"(H2), "r"(H3));
            asm volatile("st.shared.v4.b32 [%0], {%1,%2,%3,%4};"
                         :: "r"(sbase + OFF_ALO + off), "r"(L0), "r"(L1), "r"(L2), "r"(L3));
        }
        __syncthreads();

        // ---- mma over 4 k16 chunks of this half ----
#pragma unroll
        for (int kc = 0; kc < 4; kc++) {
            int kc8 = khalf*4 + kc;
            uint32_t ah[2][4], al[2][4];
#pragma unroll
            for (int mt = 0; mt < 2; mt++) {
                int row = wm*32 + mt*16 + a_row;
                int chunk = kc*2 + a_csel;
                uint32_t off = (uint32_t)(row*128 + ((chunk ^ (row & 7)) << 4));
                ldm_x4(ah[mt], sbase + OFF_AHI + off);
                ldm_x4(al[mt], sbase + OFF_ALO + off);
            }
            uint2 bh[4], bl[4];
#pragma unroll
            for (int nt = 0; nt < 4; nt++) {
                int idx = ((kc8*8 + wn*4 + nt)*32 + lane)*2;
                bh[nt] = *(const uint2*)&g_BfH[idx];
                bl[nt] = *(const uint2*)&g_BfL[idx];
            }
#pragma unroll
            for (int mt = 0; mt < 2; mt++)
#pragma unroll
                for (int nt = 0; nt < 4; nt++) {
                    mma_bf16(acc[mt][nt], ah[mt], bh[nt].x, bh[nt].y);
                    mma_bf16(acc[mt][nt], ah[mt], bl[nt].x, bl[nt].y);
                    mma_bf16(acc[mt][nt], al[mt], bh[nt].x, bh[nt].y);
                }
        }
        __syncthreads();
    }

    // ---- restage acc through smem (aliases A tables; mma reads are done) ----
    {
        int g4 = lane >> 2, q = lane & 3;
#pragma unroll
        for (int mt = 0; mt < 2; mt++)
#pragma unroll
            for (int half = 0; half < 2; half++) {
                int j = wm*32 + mt*16 + g4 + half*8;
#pragma unroll
                for (int nt = 0; nt < 4; nt++) {
                    int s = wn*32 + nt*8 + q*2;
                    *(float2*)&sAcc[j*ACC_STRIDE + s] =
                        make_float2(acc[mt][nt][half*2], acc[mt][nt][half*2+1]);
                }
            }
    }
    __syncthreads();

    // ---- coalesced epilogue: + U + V + diag*Dg; leaky-relu; * mask ----
    {
        int rsel = lane >> 3;          // 0..3
        int csel = lane & 7;           // 0..7
        const float* mrow = mask + (size_t)(b*NN + i)*NN;
        float* obase = out + ((size_t)(b*NN + i)*NN)*CC;
#pragma unroll
        for (int r4 = 0; r4 < 4; r4++) {
            int row = w*16 + r4*4 + rsel;
            float mk = mrow[row];
            bool od = (row == i);
            const float* vrow = g_V + (b*NN + row)*CC;
#pragma unroll
            for (int h = 0; h < 2; h++) {
                int col = h*32 + csel*4;
                float4 a4 = *(const float4*)&sAcc[row*ACC_STRIDE + col];
                float4 vv = *(const float4*)&vrow[col];
                float4 u4 = *(const float4*)&sU[col];
                float o0 = a4.x + u4.x + vv.x;
                float o1 = a4.y + u4.y + vv.y;
                float o2 = a4.z + u4.z + vv.z;
                float o3 = a4.w + u4.w + vv.w;
                if (od) {
                    float4 d4 = *(const float4*)&sDg[col];
                    o0 += d4.x; o1 += d4.y; o2 += d4.z; o3 += d4.w;
                }
                o0 = (o0 > 0.f) ? o0 : NEG_SLOPE * o0;
                o1 = (o1 > 0.f) ? o1 : NEG_SLOPE * o1;
                o2 = (o2 > 0.f) ? o2 : NEG_SLOPE * o2;
                o3 = (o3 > 0.f) ? o3 : NEG_SLOPE * o3;
                *(float4*)&obase[(size_t)row*CC + col] =
                    make_float4(o0*mk, o1*mk, o2*mk, o3*mk);
            }
        }
    }
}

// ---------------- launch ----------------
extern "C" void kernel_launch(void* const* d_in, const int* in_sizes, int n_in,
                              void* d_out, int out_size) {
    const float* in     = (const float*)d_in[0];
    const float* mask   = (const float*)d_in[1];
    // d_in[2] = nobj (unused: reference hard-codes average_nobj = 49)
    const float* c00    = (const float*)d_in[3];
    const float* c01    = (const float*)d_in[4];
    const float* c10    = (const float*)d_in[5];
    const float* c11    = (const float*)d_in[6];
    const float* bias   = (const float*)d_in[7];
    const float* dbias  = (const float*)d_in[8];
    float* out = (float*)d_out;

    stats_kernel<<<BB*NN, 256>>>(in, c00, c01, c10, c11);
    tw_kernel<<<BB, 256>>>(c00, c01, c10, c11);
    cgemm_kernel<<<dim3(64, 3), 256>>>(c00, c01, c10, c11, bias, dbias);
    main_mma_kernel<<<BB*NN, 256, DSM_BYTES>>>(in, mask, out);
}